// round 6
// baseline (speedup 1.0000x reference)
#include <cuda_runtime.h>
#include <cstdint>

#define NN 8192
#define EE 262144
#define HH 256
#define IND 128

// ---- scratch layout inside d_out (64M floats total; offsets mult. of 16) ----
#define OFF_H      0              // NN*HH floats
#define OFF_AGG    2097152        // NN*HH floats
#define OFF_NORM   4194304        // EE floats
#define OFF_SRC    4456448        // EE ints
#define OFF_DEG    4718592        // NN ints
#define OFF_FILL   4726784        // NN ints
#define OFF_ROWPTR 4734976        // NN+1 ints
#define OFF_DINV   4743184        // NN floats
#define OFF_EIDX   4751376        // 2*EE ints (normalized edge indices)
#define OFF_FLAG   5275664        // 1 int (1 = input is int64, 0 = int32)
// protected tail = last two output rows (written only by k_out2, after k_out1)
#define OFF_A      67092480       // NN floats (row 8190)
#define OFF_C      67100672       // NN floats (row 8191)

// ---------------- edge-index dtype detection + normalization ----------------
__global__ void k_detect(const void* __restrict__ ei, int* __restrict__ flag) {
    // If data really is int64, all values are valid node ids in [0, NN).
    // If data is int32 read as int64, values are lo + hi*2^32 -> almost surely out of range.
    const long long* e64 = (const long long*)ei;
    int ok = 1;
    for (int i = 0; i < 64; i++) {
        long long v = e64[i];
        if (v < 0 || v >= NN) { ok = 0; break; }
    }
    *flag = ok;
}

__global__ void k_cvt(const void* __restrict__ ei, const int* __restrict__ flag,
                      int* __restrict__ eidx) {
    int e = blockIdx.x * blockDim.x + threadIdx.x;
    if (e >= 2 * EE) return;
    if (*flag) eidx[e] = (int)((const long long*)ei)[e];
    else       eidx[e] = ((const int*)ei)[e];
}

// ---------------- graph preprocessing ----------------
__global__ void k_init(int* __restrict__ deg, int* __restrict__ fill) {
    int i = blockIdx.x * blockDim.x + threadIdx.x;
    if (i < NN) { deg[i] = 1; fill[i] = 0; }   // self-loop contributes 1
}

__global__ void k_hist(const int* __restrict__ eidx, int* __restrict__ deg) {
    int e = blockIdx.x * blockDim.x + threadIdx.x;
    if (e < EE) atomicAdd(&deg[eidx[EE + e]], 1);
}

__global__ void k_dinv(const int* __restrict__ deg, float* __restrict__ dinv) {
    int i = blockIdx.x * blockDim.x + threadIdx.x;
    if (i < NN) dinv[i] = rsqrtf((float)deg[i]);
}

// exclusive scan of (deg-1) over 8192 nodes; single block of 1024 threads
__global__ void k_scan(const int* __restrict__ deg, int* __restrict__ rowptr) {
    __shared__ int sh[1024];
    int t = threadIdx.x;
    int cnt[8];
    int s = 0;
#pragma unroll
    for (int i = 0; i < 8; i++) { cnt[i] = deg[t * 8 + i] - 1; s += cnt[i]; }
    sh[t] = s;
    __syncthreads();
    for (int off = 1; off < 1024; off <<= 1) {
        int v = 0;
        if (t >= off) v = sh[t - off];
        __syncthreads();
        sh[t] += v;
        __syncthreads();
    }
    int run = sh[t] - s;   // exclusive prefix
#pragma unroll
    for (int i = 0; i < 8; i++) { rowptr[t * 8 + i] = run; run += cnt[i]; }
    if (t == 1023) rowptr[NN] = run;
}

__global__ void k_fill(const int* __restrict__ eidx,
                       const int* __restrict__ rowptr,
                       int* __restrict__ fill,
                       const float* __restrict__ dinv,
                       int* __restrict__ srcIdx,
                       float* __restrict__ normv) {
    int e = blockIdx.x * blockDim.x + threadIdx.x;
    if (e >= EE) return;
    int s = eidx[e];
    int d = eidx[EE + e];
    int pos = rowptr[d] + atomicAdd(&fill[d], 1);
    srcIdx[pos] = s;
    normv[pos] = dinv[s] * dinv[d];
}

// ---- aggregation: outp[i] = dinv[i]^2*in[i] + sum_e norm[e]*in[src[e]] ----
template <int C>
__global__ void k_agg(const float* __restrict__ in,
                      float* __restrict__ outp,
                      const int* __restrict__ rowptr,
                      const int* __restrict__ srcIdx,
                      const float* __restrict__ normv,
                      const float* __restrict__ dinv) {
    int i = blockIdx.x;
    int c = threadIdx.x;          // C threads per block
    float dv = dinv[i];
    float acc = dv * dv * in[(size_t)i * C + c];
    int beg = rowptr[i], end = rowptr[i + 1];
    for (int e = beg; e < end; e++) {
        int   s = srcIdx[e];
        float w = normv[e];
        acc += w * in[(size_t)s * C + c];
    }
    outp[(size_t)i * C + c] = acc;
}

// ---- GEMM: C[m][n] = act( A[m][:] . W[n][:] + b[n] ); W is 256 x K, K-major ----
// BM=64, BN=128, BK=16, 256 threads, 4x8 per thread
template <int K, bool RELU>
__global__ void __launch_bounds__(256) k_gemm(const float* __restrict__ A,
                                              const float* __restrict__ W,
                                              const float* __restrict__ bias,
                                              float* __restrict__ C) {
    constexpr int BM = 64, BN = 128, BK = 16;
    __shared__ float As[BK][BM];
    __shared__ float Bs[BK][BN];

    int t  = threadIdx.x;
    int m0 = blockIdx.x * BM;
    int n0 = blockIdx.y * BN;
    int tm = (t >> 4) * 4;   // 0..60
    int tn = (t & 15) * 8;   // 0..120

    float acc[4][8];
#pragma unroll
    for (int i = 0; i < 4; i++)
#pragma unroll
        for (int j = 0; j < 8; j++) acc[i][j] = 0.f;

    for (int kk = 0; kk < K; kk += BK) {
        {   // A tile (64x16 = 256 float4, one per thread), transposed into As[k][m]
            int row = t >> 2, seg = t & 3;
            float4 v = *(const float4*)(A + (size_t)(m0 + row) * K + kk + seg * 4);
            As[seg * 4 + 0][row] = v.x;
            As[seg * 4 + 1][row] = v.y;
            As[seg * 4 + 2][row] = v.z;
            As[seg * 4 + 3][row] = v.w;
        }
#pragma unroll
        for (int u = 0; u < 2; u++) {   // W tile (128x16 = 512 float4)
            int idx = u * 256 + t;
            int row = idx >> 2, seg = idx & 3;
            float4 v = *(const float4*)(W + (size_t)(n0 + row) * K + kk + seg * 4);
            Bs[seg * 4 + 0][row] = v.x;
            Bs[seg * 4 + 1][row] = v.y;
            Bs[seg * 4 + 2][row] = v.z;
            Bs[seg * 4 + 3][row] = v.w;
        }
        __syncthreads();
#pragma unroll
        for (int k = 0; k < BK; k++) {
            float a[4], w[8];
            *(float4*)a       = *(const float4*)&As[k][tm];
            *(float4*)w       = *(const float4*)&Bs[k][tn];
            *(float4*)(w + 4) = *(const float4*)&Bs[k][tn + 4];
#pragma unroll
            for (int i = 0; i < 4; i++)
#pragma unroll
                for (int j = 0; j < 8; j++) acc[i][j] = fmaf(a[i], w[j], acc[i][j]);
        }
        __syncthreads();
    }

    float bb[8];
    *(float4*)bb       = *(const float4*)(bias + n0 + tn);
    *(float4*)(bb + 4) = *(const float4*)(bias + n0 + tn + 4);
#pragma unroll
    for (int i = 0; i < 4; i++) {
        float4 lo, hi;
        float* o = (float*)&lo;
        float* p = (float*)&hi;
#pragma unroll
        for (int j = 0; j < 4; j++) {
            float v0 = acc[i][j] + bb[j];
            float v1 = acc[i][j + 4] + bb[j + 4];
            if (RELU) { v0 = fmaxf(v0, 0.f); v1 = fmaxf(v1, 0.f); }
            o[j] = v0; p[j] = v1;
        }
        float* dst = C + (size_t)(m0 + tm + i) * HH + n0 + tn;
        *(float4*)dst       = lo;
        *(float4*)(dst + 4) = hi;
    }
}

// ---- head: a[i] = h[i].wi, c[i] = h[i].wj ----
__global__ void k_ac(const float* __restrict__ h, const float* __restrict__ eW,
                     float* __restrict__ av, float* __restrict__ cv) {
    int gw   = (blockIdx.x * blockDim.x + threadIdx.x) >> 5;  // warp = node
    int lane = threadIdx.x & 31;
    const float* row = h + (size_t)gw * HH;
    float sa = 0.f, sc = 0.f;
#pragma unroll
    for (int k = lane; k < HH; k += 32) {
        float v = row[k];
        sa = fmaf(v, eW[k], sa);
        sc = fmaf(v, eW[HH + k], sc);
    }
#pragma unroll
    for (int o = 16; o; o >>= 1) {
        sa += __shfl_down_sync(0xffffffffu, sa, o);
        sc += __shfl_down_sync(0xffffffffu, sc, o);
    }
    if (lane == 0) { av[gw] = sa; cv[gw] = sc; }
}

// ---- output phase 1: rows 0..8189 (a/c live in rows 8190-8191, untouched here) ----
__global__ void k_out1(const float* __restrict__ av, const float* __restrict__ cv,
                       const float* __restrict__ eb, float* __restrict__ out) {
    int i = blockIdx.x;                 // 0..8189
    float base = av[i] + eb[0];
    float4* o = (float4*)(out + (size_t)i * NN);
    const float4* c4 = (const float4*)cv;
    for (int j = threadIdx.x; j < NN / 4; j += blockDim.x) {
        float4 c = c4[j];
        o[j] = make_float4(base + c.x, base + c.y, base + c.z, base + c.w);
    }
}

// ---- output phase 2: rows 8190..8191 (single block; stage a/c in smem first) ----
__global__ void k_out2(const float* __restrict__ av, const float* __restrict__ cv,
                       const float* __restrict__ eb, float* __restrict__ out) {
    __shared__ float cs[NN];
    __shared__ float a2[2];
    int t = threadIdx.x;                // 1024 threads
    for (int j = t; j < NN; j += 1024) cs[j] = cv[j];
    if (t < 2) a2[t] = av[NN - 2 + t];
    __syncthreads();                    // everything read before any write
    float e = eb[0];
#pragma unroll
    for (int r = 0; r < 2; r++) {
        float base = a2[r] + e;
        float4* o = (float4*)(out + (size_t)(NN - 2 + r) * NN);
        const float4* c4 = (const float4*)cs;
        for (int j = t; j < NN / 4; j += 1024) {
            float4 c = c4[j];
            o[j] = make_float4(base + c.x, base + c.y, base + c.z, base + c.w);
        }
    }
}

// ---------------- launch ----------------
extern "C" void kernel_launch(void* const* d_in, const int* in_sizes, int n_in,
                              void* d_out, int out_size) {
    const float* x    = (const float*)d_in[0];
    const void*  ei   = d_in[1];                 // int64 or int32 — detected on device
    const float* W0   = (const float*)d_in[2];
    const float* b0   = (const float*)d_in[3];
    const float* W1   = (const float*)d_in[4];
    const float* b1   = (const float*)d_in[5];
    const float* W2   = (const float*)d_in[6];
    const float* b2   = (const float*)d_in[7];
    const float* oW   = (const float*)d_in[8];
    const float* ob   = (const float*)d_in[9];
    const float* eW   = (const float*)d_in[10];
    const float* ebias= (const float*)d_in[11];
    float* out = (float*)d_out;

    // scratch carved from d_out (no device globals, no allocation)
    float* h      = out + OFF_H;
    float* agg    = out + OFF_AGG;
    float* normv  = out + OFF_NORM;
    int*   srcIdx = (int*)(out + OFF_SRC);
    int*   deg    = (int*)(out + OFF_DEG);
    int*   fill   = (int*)(out + OFF_FILL);
    int*   rowptr = (int*)(out + OFF_ROWPTR);
    float* dinv   = out + OFF_DINV;
    int*   eidx   = (int*)(out + OFF_EIDX);
    int*   flag   = (int*)(out + OFF_FLAG);
    float* av     = out + OFF_A;   // row 8190 of the output (protected tail)
    float* cv     = out + OFF_C;   // row 8191 of the output (protected tail)

    // edge-index normalization (handles int64 OR int32 input)
    k_detect<<<1, 1>>>(ei, flag);
    k_cvt<<<2 * EE / 256, 256>>>(ei, flag, eidx);

    // graph preprocessing
    k_init<<<NN / 256, 256>>>(deg, fill);
    k_hist<<<EE / 256, 256>>>(eidx, deg);
    k_dinv<<<NN / 256, 256>>>(deg, dinv);
    k_scan<<<1, 1024>>>(deg, rowptr);
    k_fill<<<EE / 256, 256>>>(eidx, rowptr, fill, dinv, srcIdx, normv);

    dim3 ggrid(NN / 64, HH / 128);

    // layer 0: aggregate x (128 cols) then GEMM to 256
    k_agg<IND><<<NN, IND>>>(x, agg, rowptr, srcIdx, normv, dinv);
    k_gemm<IND, true><<<ggrid, 256>>>(agg, W0, b0, h);
    // layer 1
    k_agg<HH><<<NN, HH>>>(h, agg, rowptr, srcIdx, normv, dinv);
    k_gemm<HH, true><<<ggrid, 256>>>(agg, W1, b1, h);
    // layer 2
    k_agg<HH><<<NN, HH>>>(h, agg, rowptr, srcIdx, normv, dinv);
    k_gemm<HH, true><<<ggrid, 256>>>(agg, W2, b2, h);
    // output linear (no relu): h -> agg
    k_gemm<HH, false><<<ggrid, 256>>>(h, oW, ob, agg);
    // head: per-node dot products into the protected tail rows
    k_ac<<<NN * 32 / 256, 256>>>(agg, eW, av, cv);
    // outer-sum output: phase 1 (rows 0..8189), then phase 2 (rows 8190..8191)
    k_out1<<<NN - 2, 256>>>(av, cv, ebias, out);
    k_out2<<<1, 1024>>>(av, cv, ebias, out);
}